// round 1
// baseline (speedup 1.0000x reference)
#include <cuda_runtime.h>

// Problem dims (fixed by setup_inputs; t input is always 128)
#define NB 256      // batch
#define HD 1024     // hidden
#define DD 256      // fc out dim
#define TT 128      // timesteps
#define KD HD       // GEMM K
#define KT 32       // K tile

// Scratch state (static device allocations — no cudaMalloc allowed)
__device__ float g_Wc[4 * HD * HD];            // W_ih + W_hh   (16 MB)
__device__ float g_bc[4 * HD];                 // b_ih + b_hh
__device__ float g_c[NB * HD];                 // cell state
__device__ float g_h[(size_t)TT * NB * HD];    // all hidden states (128 MB)

__global__ void prep_kernel(const float* __restrict__ Wih, const float* __restrict__ Whh,
                            const float* __restrict__ bih, const float* __restrict__ bhh) {
    int i = blockIdx.x * blockDim.x + threadIdx.x;
    if (i < 4 * HD * HD) g_Wc[i] = Wih[i] + Whh[i];
    if (i < 4 * HD)      g_bc[i] = bih[i] + bhh[i];
    if (i < NB * HD)     g_c[i] = 0.0f;
}

__device__ __forceinline__ float sigm(float z) { return 1.0f / (1.0f + __expf(-z)); }

// One LSTM step, fused GEMM + pointwise.
// Block tile: 128 batch rows x 16 hidden units (= 64 gate columns: 4 gates x 16).
// grid = (HD/16 = 64, NB/128 = 2), 256 threads.
// Thread (tx in 0..15 -> hidden unit, ty in 0..15 -> 8 batch rows), acc[8 rows][4 gates].
__global__ __launch_bounds__(256) void lstm_step(int t, const float* __restrict__ hT,
                                                 const float* __restrict__ Wext) {
    __shared__ float As[KT][129];   // [k][batch row], pad 129 -> conflict-free fill/read
    __shared__ float Bs[KT][65];    // [k][gate col]

    const float* x = (t == 0) ? hT : (g_h + (size_t)(t - 1) * NB * HD);
    const float* W = Wext ? Wext : g_Wc;   // step 0: W_ih only (hx = 0); else W_comb
    float* hout = g_h + (size_t)t * NB * HD;

    int tid = threadIdx.x;
    int tx = tid & 15;
    int ty = tid >> 4;
    int n0 = blockIdx.y * 128;
    int j0 = blockIdx.x * 16;

    float acc[8][4];
#pragma unroll
    for (int r = 0; r < 8; ++r)
#pragma unroll
        for (int g = 0; g < 4; ++g) acc[r][g] = 0.0f;

    for (int kt = 0; kt < KD / KT; ++kt) {
        int k0 = kt * KT;
        __syncthreads();
        // Fill A tile: 128 rows x 32 k (transposed into As[k][row])
#pragma unroll
        for (int i = 0; i < 4; ++i) {
            int p = tid + i * 256;          // p < 1024
            int row = p >> 3, kq = p & 7;
            float4 v = *reinterpret_cast<const float4*>(
                x + (size_t)(n0 + row) * KD + k0 + kq * 4);
            As[kq * 4 + 0][row] = v.x;
            As[kq * 4 + 1][row] = v.y;
            As[kq * 4 + 2][row] = v.z;
            As[kq * 4 + 3][row] = v.w;
        }
        // Fill B tile: 64 gate rows x 32 k. gate col c = gate*16 + cc -> W row gate*HD + j0 + cc
#pragma unroll
        for (int i = 0; i < 2; ++i) {
            int p = tid + i * 256;          // p < 512
            int c = p >> 3, kq = p & 7;
            int gate = c >> 4, cc = c & 15;
            float4 v = *reinterpret_cast<const float4*>(
                W + (size_t)(gate * HD + j0 + cc) * KD + k0 + kq * 4);
            Bs[kq * 4 + 0][c] = v.x;
            Bs[kq * 4 + 1][c] = v.y;
            Bs[kq * 4 + 2][c] = v.z;
            Bs[kq * 4 + 3][c] = v.w;
        }
        __syncthreads();
#pragma unroll 8
        for (int kk = 0; kk < KT; ++kk) {
            float a[8], b[4];
#pragma unroll
            for (int r = 0; r < 8; ++r) a[r] = As[kk][ty * 8 + r];
#pragma unroll
            for (int g = 0; g < 4; ++g) b[g] = Bs[kk][g * 16 + tx];
#pragma unroll
            for (int r = 0; r < 8; ++r)
#pragma unroll
                for (int g = 0; g < 4; ++g) acc[r][g] = fmaf(a[r], b[g], acc[r][g]);
        }
    }

    // Fused LSTM pointwise: this block owns complete (i,f,g,o) for its hidden units.
    int j = j0 + tx;
    float bi = g_bc[j], bf = g_bc[HD + j], bg = g_bc[2 * HD + j], bo = g_bc[3 * HD + j];
#pragma unroll
    for (int r = 0; r < 8; ++r) {
        int n = n0 + ty * 8 + r;
        float iv = sigm(acc[r][0] + bi);
        float fv = sigm(acc[r][1] + bf);
        float gv = tanhf(acc[r][2] + bg);
        float ov = sigm(acc[r][3] + bo);
        size_t cidx = (size_t)n * HD + j;
        float cn = fv * g_c[cidx] + iv * gv;
        g_c[cidx] = cn;
        hout[cidx] = ov * tanhf(cn);
    }
}

// Final FC: out[t,n,d] = h[t,n,:] . W_fc[d,:] + b_fc[d]
// M = TT*NB = 32768 rows of g_h, K = 1024, 256 cols.
// Same tiling: 128 rows x 64 cols per block, grid = (DD/64 = 4, 32768/128 = 256).
__global__ __launch_bounds__(256) void fc_kernel(const float* __restrict__ Wfc,
                                                 const float* __restrict__ bfc,
                                                 float* __restrict__ out) {
    __shared__ float As[KT][129];
    __shared__ float Bs[KT][65];

    int tid = threadIdx.x;
    int tx = tid & 15;
    int ty = tid >> 4;
    int m0 = blockIdx.y * 128;
    int d0 = blockIdx.x * 64;

    float acc[8][4];
#pragma unroll
    for (int r = 0; r < 8; ++r)
#pragma unroll
        for (int g = 0; g < 4; ++g) acc[r][g] = 0.0f;

    for (int kt = 0; kt < KD / KT; ++kt) {
        int k0 = kt * KT;
        __syncthreads();
#pragma unroll
        for (int i = 0; i < 4; ++i) {
            int p = tid + i * 256;
            int row = p >> 3, kq = p & 7;
            float4 v = *reinterpret_cast<const float4*>(
                g_h + (size_t)(m0 + row) * KD + k0 + kq * 4);
            As[kq * 4 + 0][row] = v.x;
            As[kq * 4 + 1][row] = v.y;
            As[kq * 4 + 2][row] = v.z;
            As[kq * 4 + 3][row] = v.w;
        }
#pragma unroll
        for (int i = 0; i < 2; ++i) {
            int p = tid + i * 256;
            int c = p >> 3, kq = p & 7;
            float4 v = *reinterpret_cast<const float4*>(
                Wfc + (size_t)(d0 + c) * KD + k0 + kq * 4);
            Bs[kq * 4 + 0][c] = v.x;
            Bs[kq * 4 + 1][c] = v.y;
            Bs[kq * 4 + 2][c] = v.z;
            Bs[kq * 4 + 3][c] = v.w;
        }
        __syncthreads();
#pragma unroll 8
        for (int kk = 0; kk < KT; ++kk) {
            float a[8], b[4];
#pragma unroll
            for (int r = 0; r < 8; ++r) a[r] = As[kk][ty * 8 + r];
#pragma unroll
            for (int g = 0; g < 4; ++g) b[g] = Bs[kk][g * 16 + tx];
#pragma unroll
            for (int r = 0; r < 8; ++r)
#pragma unroll
                for (int g = 0; g < 4; ++g) acc[r][g] = fmaf(a[r], b[g], acc[r][g]);
        }
    }

#pragma unroll
    for (int r = 0; r < 8; ++r) {
        int m = m0 + ty * 8 + r;
#pragma unroll
        for (int g = 0; g < 4; ++g) {
            int d = d0 + g * 16 + tx;
            out[(size_t)m * DD + d] = acc[r][g] + bfc[d];
        }
    }
}

extern "C" void kernel_launch(void* const* d_in, const int* in_sizes, int n_in,
                              void* d_out, int out_size) {
    const float* hT  = (const float*)d_in[0];
    // d_in[1] = t (int32 scalar) — fixed at 128 for this problem; T hardcoded.
    const float* Wih = (const float*)d_in[2];
    const float* Whh = (const float*)d_in[3];
    const float* bih = (const float*)d_in[4];
    const float* bhh = (const float*)d_in[5];
    const float* Wfc = (const float*)d_in[6];
    const float* bfc = (const float*)d_in[7];
    float* out = (float*)d_out;

    // W_comb = W_ih + W_hh, b_comb = b_ih + b_hh, zero cell state (every call: graph-replay safe)
    prep_kernel<<<(4 * HD * HD + 255) / 256, 256>>>(Wih, Whh, bih, bhh);

    dim3 sgrid(HD / 16, NB / 128);   // (64, 2) = 128 blocks
    // Step 0: x = hT, hx = 0  ->  gates = hT @ W_ih^T + (b_ih + b_hh)
    lstm_step<<<sgrid, 256>>>(0, hT, Wih);
    // Steps t>=1: x == hx == h_{t-1}  ->  gates = h @ (W_ih + W_hh)^T + (b_ih + b_hh)
    for (int t = 1; t < TT; ++t) lstm_step<<<sgrid, 256>>>(t, hT, nullptr);

    fc_kernel<<<dim3(DD / 64, (TT * NB) / 128), 256>>>(Wfc, bfc, out);
}